// round 1
// baseline (speedup 1.0000x reference)
#include <cuda_runtime.h>
#include <cstdint>

// Problem dims (fixed by setup_inputs)
#define BATCH 4
#define NG 64
#define NP 4096
#define NH 8
#define H1 128
#define H2 64
#define PCHUNK 256   // p points per block
#define RPI 8        // rows processed per warp iteration
#define WARPS 8

struct __align__(16) Smem {
    float2 W2p[64 * 64];          // [k2][c] = {W2[2k2][c], W2[2k2+1][c]}  32 KB
    float2 W3p[32 * 8];           // [c2][h] = {W3[2c2][h], W3[2c2+1][h]}   2 KB
    float  W1s[4 * 128];          // 2 KB
    float  b1s[128], g1s[128], be1s[128];
    float  b2s[64],  g2s[64],  be2s[64];
    float  b3s[8],   bss[8];
    float  sx[PCHUNK], sy[PCHUNK], sz[PCHUNK];
    float  scratch[WARPS][RPI * 128];   // hb (h1 tile) aliased with h2 buffer; 32 KB
    float  obuf[WARPS][8 * 36];         // staged outputs: [h][pitch 36] over 32 p's
};

__device__ __forceinline__ uint64_t ffma2(uint64_t a, uint64_t b, uint64_t c) {
    uint64_t d;
    asm("fma.rn.f32x2 %0, %1, %2, %3;" : "=l"(d) : "l"(a), "l"(b), "l"(c));
    return d;
}
__device__ __forceinline__ float lo32(uint64_t v) { return __uint_as_float((unsigned)(v & 0xffffffffu)); }
__device__ __forceinline__ float hi32(uint64_t v) { return __uint_as_float((unsigned)(v >> 32)); }

__global__ void __launch_bounds__(256, 2)
gab_kernel(const float* __restrict__ scene,   // (B, NP, 3)
           const float* __restrict__ poses,   // (B, NG, 7)
           const float* __restrict__ W1, const float* __restrict__ b1,
           const float* __restrict__ g1, const float* __restrict__ be1,
           const float* __restrict__ W2, const float* __restrict__ b2,
           const float* __restrict__ g2, const float* __restrict__ be2,
           const float* __restrict__ W3, const float* __restrict__ b3,
           const float* __restrict__ bscale,
           float* __restrict__ out)            // (B, NH, NG, NP)
{
    extern __shared__ __align__(16) char smraw[];
    Smem& sm = *reinterpret_cast<Smem*>(smraw);

    const int tid = threadIdx.x;
    const int b = blockIdx.z;
    const int gbase = blockIdx.y * 8;
    const int p0 = blockIdx.x * PCHUNK;

    // ---- Stage weights / scene chunk into shared ----
    for (int idx = tid; idx < 64 * 64; idx += 256) {
        int k2 = idx >> 6, c = idx & 63;
        sm.W2p[idx] = make_float2(W2[(2 * k2) * 64 + c], W2[(2 * k2 + 1) * 64 + c]);
    }
    if (tid < 256) {
        int c2 = tid >> 3, h = tid & 7;
        sm.W3p[tid] = make_float2(W3[(2 * c2) * 8 + h], W3[(2 * c2 + 1) * 8 + h]);
    }
    for (int idx = tid; idx < 512; idx += 256) sm.W1s[idx] = W1[idx];
    if (tid < 128) { sm.b1s[tid] = b1[tid]; sm.g1s[tid] = g1[tid]; sm.be1s[tid] = be1[tid]; }
    if (tid < 64)  { sm.b2s[tid] = b2[tid]; sm.g2s[tid] = g2[tid]; sm.be2s[tid] = be2[tid]; }
    if (tid < 8)   { sm.b3s[tid] = b3[tid]; sm.bss[tid] = bscale[tid]; }
    if (tid < PCHUNK) {
        const float* spp = scene + ((size_t)b * NP + p0 + tid) * 3;
        sm.sx[tid] = spp[0]; sm.sy[tid] = spp[1]; sm.sz[tid] = spp[2];
    }
    __syncthreads();

    const int wid = tid >> 5, lane = tid & 31;
    const int g = gbase + wid;

    // Per-warp pose -> rotation (all lanes redundantly; once per 256 rows)
    const float* pp = poses + ((size_t)(b * NG + g)) * 7;
    float tx = pp[0], ty = pp[1], tz = pp[2];
    float qx = pp[3], qy = pp[4], qz = pp[5], qw = pp[6];
    float inv = 1.f / (sqrtf(qx * qx + qy * qy + qz * qz + qw * qw) + 1e-8f);
    qx *= inv; qy *= inv; qz *= inv; qw *= inv;
    float xx = qx * qx, yy = qy * qy, zz = qz * qz;
    float xy = qx * qy, xz = qx * qz, yz = qy * qz;
    float wx = qw * qx, wy = qw * qy, wz = qw * qz;
    // R rows per reference; rel_local_i = sum_j R[j][i] * rel_j  (R^T applied)
    float R00 = 1.f - 2.f * (yy + zz), R01 = 2.f * (xy - wz), R02 = 2.f * (xz + wy);
    float R10 = 2.f * (xy + wz), R11 = 1.f - 2.f * (xx + zz), R12 = 2.f * (yz - wx);
    float R20 = 2.f * (xz - wy), R21 = 2.f * (yz + wx), R22 = 1.f - 2.f * (xx + yy);

    float* hb  = sm.scratch[wid];     // h1 tile: [r][128]
    float* h2b = sm.scratch[wid];     // aliased: h2 tile [r][pitch 66]
    float* ob  = sm.obuf[wid];        // [h][pitch 36]

    const size_t outbase = (((size_t)b * NH) * NG + g) * NP + p0;  // + h*NG*NP + p
    const int hD = lane & 7, r0D = lane >> 3;

    const uint64_t* w2u = reinterpret_cast<const uint64_t*>(sm.W2p);
    const uint64_t* w3u = reinterpret_cast<const uint64_t*>(sm.W3p);

    for (int it = 0; it < PCHUNK / RPI; ++it) {
        const int pl_base = it * RPI;

        // ---- Stage B: feats -> h1 (relu+LN), per row ----
        #pragma unroll 2
        for (int r = 0; r < RPI; ++r) {
            int pl = pl_base + r;
            float rx = sm.sx[pl] - tx, ry = sm.sy[pl] - ty, rz = sm.sz[pl] - tz;
            float lx = R00 * rx + R10 * ry + R20 * rz;
            float ly = R01 * rx + R11 * ry + R21 * rz;
            float lz = R02 * rx + R12 * ry + R22 * rz;
            float dd = sqrtf(lx * lx + ly * ly + lz * lz);
            float v[4]; float s = 0.f, s2 = 0.f;
            #pragma unroll
            for (int m = 0; m < 4; ++m) {
                int j = lane + 32 * m;
                float a = sm.b1s[j] + lx * sm.W1s[j] + ly * sm.W1s[128 + j]
                                    + lz * sm.W1s[256 + j] + dd * sm.W1s[384 + j];
                a = fmaxf(a, 0.f);
                v[m] = a; s += a; s2 += a * a;
            }
            #pragma unroll
            for (int o = 16; o; o >>= 1) {
                s  += __shfl_xor_sync(0xffffffffu, s,  o);
                s2 += __shfl_xor_sync(0xffffffffu, s2, o);
            }
            float mu = s * (1.f / 128.f);
            float rs = rsqrtf(fmaxf(s2 * (1.f / 128.f) - mu * mu, 0.f) + 1e-5f);
            #pragma unroll
            for (int m = 0; m < 4; ++m) {
                int j = lane + 32 * m;
                hb[r * 128 + j] = (v[m] - mu) * rs * sm.g1s[j] + sm.be1s[j];
            }
        }
        __syncwarp();

        // ---- Stage C: h1 @ W2 mini-GEMM (8 rows x 2 cols/lane), packed f32x2 over K ----
        uint64_t acc[RPI][2];
        #pragma unroll
        for (int r = 0; r < RPI; ++r) { acc[r][0] = 0ull; acc[r][1] = 0ull; }
        const uint64_t* hb2 = reinterpret_cast<const uint64_t*>(hb);
        #pragma unroll 4
        for (int k2 = 0; k2 < 64; ++k2) {
            uint64_t w0 = w2u[k2 * 64 + lane];
            uint64_t w1 = w2u[k2 * 64 + lane + 32];
            #pragma unroll
            for (int r = 0; r < RPI; ++r) {
                uint64_t hp = hb2[r * 64 + k2];  // broadcast
                acc[r][0] = ffma2(hp, w0, acc[r][0]);
                acc[r][1] = ffma2(hp, w1, acc[r][1]);
            }
        }
        __syncwarp();  // hb fully consumed; region reused as h2b below

        // epilogue: bias, relu, LN over 64, store h2 tile
        #pragma unroll 2
        for (int r = 0; r < RPI; ++r) {
            float v0 = lo32(acc[r][0]) + hi32(acc[r][0]) + sm.b2s[lane];
            float v1 = lo32(acc[r][1]) + hi32(acc[r][1]) + sm.b2s[lane + 32];
            v0 = fmaxf(v0, 0.f); v1 = fmaxf(v1, 0.f);
            float s = v0 + v1, s2 = v0 * v0 + v1 * v1;
            #pragma unroll
            for (int o = 16; o; o >>= 1) {
                s  += __shfl_xor_sync(0xffffffffu, s,  o);
                s2 += __shfl_xor_sync(0xffffffffu, s2, o);
            }
            float mu = s * (1.f / 64.f);
            float rs = rsqrtf(fmaxf(s2 * (1.f / 64.f) - mu * mu, 0.f) + 1e-5f);
            h2b[r * 66 + lane]      = (v0 - mu) * rs * sm.g2s[lane]      + sm.be2s[lane];
            h2b[r * 66 + lane + 32] = (v1 - mu) * rs * sm.g2s[lane + 32] + sm.be2s[lane + 32];
        }
        __syncwarp();

        // ---- Stage D: h2 @ W3 — lane handles (h = lane&7, rows r0D and r0D+4) ----
        uint64_t a0 = 0ull, a1 = 0ull;
        const uint64_t* h0 = reinterpret_cast<const uint64_t*>(h2b + r0D * 66);
        const uint64_t* h1p = reinterpret_cast<const uint64_t*>(h2b + (r0D + 4) * 66);
        #pragma unroll 8
        for (int c2 = 0; c2 < 32; ++c2) {
            uint64_t wp = w3u[c2 * 8 + hD];
            a0 = ffma2(h0[c2], wp, a0);
            a1 = ffma2(h1p[c2], wp, a1);
        }
        float o0 = (lo32(a0) + hi32(a0) + sm.b3s[hD]) * sm.bss[hD];
        float o1 = (lo32(a1) + hi32(a1) + sm.b3s[hD]) * sm.bss[hD];
        int sub = it & 3;
        ob[hD * 36 + sub * 8 + r0D]     = o0;
        ob[hD * 36 + sub * 8 + r0D + 4] = o1;

        if (sub == 3) {
            __syncwarp();
            int pw = pl_base - 24;  // start of this 32-p window
            #pragma unroll
            for (int h = 0; h < 8; ++h)
                out[outbase + (size_t)h * (NG * NP) + pw + lane] = ob[h * 36 + lane];
        }
        __syncwarp();  // order stage-D reads of h2b before next iter's hb writes
    }
}

extern "C" void kernel_launch(void* const* d_in, const int* in_sizes, int n_in,
                              void* d_out, int out_size) {
    // metadata order: grasp_tokens, scene_points, grasp_poses, W1, b1, g1, beta1,
    //                 W2, b2, g2, beta2, W3, b3, bias_scale
    const float* scene  = (const float*)d_in[1];
    const float* poses  = (const float*)d_in[2];
    const float* W1     = (const float*)d_in[3];
    const float* b1     = (const float*)d_in[4];
    const float* g1     = (const float*)d_in[5];
    const float* be1    = (const float*)d_in[6];
    const float* W2     = (const float*)d_in[7];
    const float* b2     = (const float*)d_in[8];
    const float* g2     = (const float*)d_in[9];
    const float* be2    = (const float*)d_in[10];
    const float* W3     = (const float*)d_in[11];
    const float* b3     = (const float*)d_in[12];
    const float* bscale = (const float*)d_in[13];
    float* out = (float*)d_out;

    cudaFuncSetAttribute(gab_kernel, cudaFuncAttributeMaxDynamicSharedMemorySize,
                         (int)sizeof(Smem));
    dim3 grid(NP / PCHUNK, NG / 8, BATCH);
    gab_kernel<<<grid, 256, sizeof(Smem)>>>(scene, poses, W1, b1, g1, be1,
                                            W2, b2, g2, be2, W3, b3, bscale, out);
}

// round 3
// speedup vs baseline: 1.1038x; 1.1038x over previous
#include <cuda_runtime.h>
#include <cstdint>

// Problem dims (fixed by setup_inputs)
#define BATCH 4
#define NG 64
#define NP 4096
#define NH 8
#define PCHUNK 256   // p points per block
#define RPI 8        // rows per warp iteration
#define WARPS 8

struct __align__(16) Smem {
    float4 W2v[32 * 64];          // [k4][c] = {W2[4k4..4k4+3][c]}   32 KB
    float4 W3v[16 * 8];           // [c4][h] = {W3[4c4..4c4+3][h]}    2 KB
    float4 sp[PCHUNK];            // scene points {x,y,z,0}           4 KB
    float  scratch[WARPS][RPI * 128];  // hb (h1, pitch 128) aliased with h2 (pitch 68); 32 KB
    float  obuf[WARPS][8 * 36];        // staged outputs               9 KB
};

__device__ __forceinline__ uint64_t ffma2(uint64_t a, uint64_t b, uint64_t c) {
    uint64_t d;
    asm("fma.rn.f32x2 %0, %1, %2, %3;" : "=l"(d) : "l"(a), "l"(b), "l"(c));
    return d;
}
__device__ __forceinline__ float lo32(uint64_t v) { return __uint_as_float((unsigned)(v & 0xffffffffu)); }
__device__ __forceinline__ float hi32(uint64_t v) { return __uint_as_float((unsigned)(v >> 32)); }

__global__ void __launch_bounds__(256, 2)
gab_kernel(const float* __restrict__ scene,   // (B, NP, 3)
           const float* __restrict__ poses,   // (B, NG, 7)
           const float* __restrict__ W1, const float* __restrict__ b1,
           const float* __restrict__ g1, const float* __restrict__ be1,
           const float* __restrict__ W2, const float* __restrict__ b2,
           const float* __restrict__ g2, const float* __restrict__ be2,
           const float* __restrict__ W3, const float* __restrict__ b3,
           const float* __restrict__ bscale,
           float* __restrict__ out)            // (B, NH, NG, NP)
{
    extern __shared__ __align__(16) char smraw[];
    Smem& sm = *reinterpret_cast<Smem*>(smraw);

    const int tid = threadIdx.x;
    const int b = blockIdx.z;
    const int gbase = blockIdx.y * 8;
    const int p0 = blockIdx.x * PCHUNK;

    // ---- Stage shared: repacked W2 (float4 over K), W3, scene chunk ----
    for (int idx = tid; idx < 32 * 64; idx += 256) {
        int k4 = idx >> 6, c = idx & 63;
        sm.W2v[idx] = make_float4(W2[(4 * k4 + 0) * 64 + c], W2[(4 * k4 + 1) * 64 + c],
                                  W2[(4 * k4 + 2) * 64 + c], W2[(4 * k4 + 3) * 64 + c]);
    }
    if (tid < 128) {
        int c4 = tid >> 3, h = tid & 7;
        sm.W3v[tid] = make_float4(W3[(4 * c4 + 0) * 8 + h], W3[(4 * c4 + 1) * 8 + h],
                                  W3[(4 * c4 + 2) * 8 + h], W3[(4 * c4 + 3) * 8 + h]);
    }
    if (tid < PCHUNK) {
        const float* spp = scene + ((size_t)b * NP + p0 + tid) * 3;
        sm.sp[tid] = make_float4(spp[0], spp[1], spp[2], 0.f);
    }
    __syncthreads();

    const int wid = tid >> 5, lane = tid & 31;
    const int g = gbase + wid;
    const int hD = lane & 7, r0D = lane >> 3;

    // ---- Register-cached small weights (lane-invariant across all rows) ----
    float w1r0[4], w1r1[4], w1r2[4], w1r3[4], b1r[4], g1r[4], be1r[4];
    #pragma unroll
    for (int m = 0; m < 4; ++m) {
        int j = lane + 32 * m;
        w1r0[m] = __ldg(W1 + j);       w1r1[m] = __ldg(W1 + 128 + j);
        w1r2[m] = __ldg(W1 + 256 + j); w1r3[m] = __ldg(W1 + 384 + j);
        b1r[m] = __ldg(b1 + j); g1r[m] = __ldg(g1 + j); be1r[m] = __ldg(be1 + j);
    }
    const float b2r0 = __ldg(b2 + lane),  b2r1 = __ldg(b2 + lane + 32);
    const float g2r0 = __ldg(g2 + lane),  g2r1 = __ldg(g2 + lane + 32);
    const float be2r0 = __ldg(be2 + lane), be2r1 = __ldg(be2 + lane + 32);
    const float b3r = __ldg(b3 + hD), bsr = __ldg(bscale + hD);

    // Per-warp pose -> rotation
    const float* pp = poses + ((size_t)(b * NG + g)) * 7;
    float tx = pp[0], ty = pp[1], tz = pp[2];
    float qx = pp[3], qy = pp[4], qz = pp[5], qw = pp[6];
    float inv = 1.f / (sqrtf(qx * qx + qy * qy + qz * qz + qw * qw) + 1e-8f);
    qx *= inv; qy *= inv; qz *= inv; qw *= inv;
    float xx = qx * qx, yy = qy * qy, zz = qz * qz;
    float xy = qx * qy, xz = qx * qz, yz = qy * qz;
    float wx = qw * qx, wy = qw * qy, wz = qw * qz;
    float R00 = 1.f - 2.f * (yy + zz), R01 = 2.f * (xy - wz), R02 = 2.f * (xz + wy);
    float R10 = 2.f * (xy + wz), R11 = 1.f - 2.f * (xx + zz), R12 = 2.f * (yz - wx);
    float R20 = 2.f * (xz - wy), R21 = 2.f * (yz + wx), R22 = 1.f - 2.f * (xx + yy);

    float* hb  = sm.scratch[wid];     // h1 tile: [r][128]
    float* h2b = sm.scratch[wid];     // aliased: h2 tile [r][pitch 68]
    float* ob  = sm.obuf[wid];

    const size_t outbase = (((size_t)b * NH) * NG + g) * NP + p0;

    const ulonglong2* w2u = reinterpret_cast<const ulonglong2*>(sm.W2v);
    const ulonglong2* w3u = reinterpret_cast<const ulonglong2*>(sm.W3v);

    for (int it = 0; it < PCHUNK / RPI; ++it) {
        const int pl_base = it * RPI;

        // ---- Stage B: feats -> h1 (relu + LN) ----
        #pragma unroll 2
        for (int r = 0; r < RPI; ++r) {
            float4 P = sm.sp[pl_base + r];
            float rx = P.x - tx, ry = P.y - ty, rz = P.z - tz;
            float lx = R00 * rx + R10 * ry + R20 * rz;
            float ly = R01 * rx + R11 * ry + R21 * rz;
            float lz = R02 * rx + R12 * ry + R22 * rz;
            float dd = sqrtf(lx * lx + ly * ly + lz * lz);
            float v[4]; float s = 0.f, s2 = 0.f;
            #pragma unroll
            for (int m = 0; m < 4; ++m) {
                float a = fmaf(dd, w1r3[m], b1r[m]);
                a = fmaf(lz, w1r2[m], a);
                a = fmaf(ly, w1r1[m], a);
                a = fmaf(lx, w1r0[m], a);
                a = fmaxf(a, 0.f);
                v[m] = a; s += a; s2 = fmaf(a, a, s2);
            }
            #pragma unroll
            for (int o = 16; o; o >>= 1) {
                s  += __shfl_xor_sync(0xffffffffu, s,  o);
                s2 += __shfl_xor_sync(0xffffffffu, s2, o);
            }
            float mu = s * (1.f / 128.f);
            float rs = rsqrtf(fmaxf(s2 * (1.f / 128.f) - mu * mu, 0.f) + 1e-5f);
            #pragma unroll
            for (int m = 0; m < 4; ++m)
                hb[r * 128 + lane + 32 * m] = fmaf((v[m] - mu) * rs, g1r[m], be1r[m]);
        }
        __syncwarp();

        // ---- Stage C: h1 @ W2, float4 K-packing, ffma2 ----
        uint64_t acc[RPI][2];
        #pragma unroll
        for (int r = 0; r < RPI; ++r) { acc[r][0] = 0ull; acc[r][1] = 0ull; }
        const ulonglong2* hb4 = reinterpret_cast<const ulonglong2*>(hb);
        #pragma unroll 4
        for (int k4 = 0; k4 < 32; ++k4) {
            ulonglong2 wa = w2u[k4 * 64 + lane];
            ulonglong2 wb = w2u[k4 * 64 + lane + 32];
            #pragma unroll
            for (int r = 0; r < RPI; ++r) {
                ulonglong2 hp = hb4[r * 32 + k4];   // broadcast, 4 K-values
                acc[r][0] = ffma2(hp.x, wa.x, acc[r][0]);
                acc[r][0] = ffma2(hp.y, wa.y, acc[r][0]);
                acc[r][1] = ffma2(hp.x, wb.x, acc[r][1]);
                acc[r][1] = ffma2(hp.y, wb.y, acc[r][1]);
            }
        }
        __syncwarp();  // hb fully consumed; region reused as h2b

        // epilogue: bias, relu, LN over 64, store h2 tile
        #pragma unroll 2
        for (int r = 0; r < RPI; ++r) {
            float v0 = lo32(acc[r][0]) + hi32(acc[r][0]) + b2r0;
            float v1 = lo32(acc[r][1]) + hi32(acc[r][1]) + b2r1;
            v0 = fmaxf(v0, 0.f); v1 = fmaxf(v1, 0.f);
            float s = v0 + v1;
            float s2 = fmaf(v0, v0, v1 * v1);
            #pragma unroll
            for (int o = 16; o; o >>= 1) {
                s  += __shfl_xor_sync(0xffffffffu, s,  o);
                s2 += __shfl_xor_sync(0xffffffffu, s2, o);
            }
            float mu = s * (1.f / 64.f);
            float rs = rsqrtf(fmaxf(s2 * (1.f / 64.f) - mu * mu, 0.f) + 1e-5f);
            h2b[r * 68 + lane]      = fmaf((v0 - mu) * rs, g2r0, be2r0);
            h2b[r * 68 + lane + 32] = fmaf((v1 - mu) * rs, g2r1, be2r1);
        }
        __syncwarp();

        // ---- Stage D: h2 @ W3 — lane = (h = lane&7, rows r0D, r0D+4), float4 packed ----
        uint64_t a0 = 0ull, a1 = 0ull;
        const ulonglong2* h0  = reinterpret_cast<const ulonglong2*>(h2b + r0D * 68);
        const ulonglong2* h1p = reinterpret_cast<const ulonglong2*>(h2b + (r0D + 4) * 68);
        #pragma unroll
        for (int c4 = 0; c4 < 16; ++c4) {
            ulonglong2 wp = w3u[c4 * 8 + hD];
            ulonglong2 ha = h0[c4];
            ulonglong2 hc = h1p[c4];
            a0 = ffma2(ha.x, wp.x, a0);
            a0 = ffma2(ha.y, wp.y, a0);
            a1 = ffma2(hc.x, wp.x, a1);
            a1 = ffma2(hc.y, wp.y, a1);
        }
        float o0 = (lo32(a0) + hi32(a0) + b3r) * bsr;
        float o1 = (lo32(a1) + hi32(a1) + b3r) * bsr;
        int sub = it & 3;
        ob[hD * 36 + sub * 8 + r0D]     = o0;
        ob[hD * 36 + sub * 8 + r0D + 4] = o1;

        if (sub == 3) {
            __syncwarp();
            int pw = pl_base - 24;  // start of this 32-p window
            #pragma unroll
            for (int h = 0; h < 8; ++h)
                out[outbase + (size_t)h * (NG * NP) + pw + lane] = ob[h * 36 + lane];
        }
        __syncwarp();  // order stage-D reads before next iter's hb writes
    }
}

extern "C" void kernel_launch(void* const* d_in, const int* in_sizes, int n_in,
                              void* d_out, int out_size) {
    // metadata order: grasp_tokens, scene_points, grasp_poses, W1, b1, g1, beta1,
    //                 W2, b2, g2, beta2, W3, b3, bias_scale
    const float* scene  = (const float*)d_in[1];
    const float* poses  = (const float*)d_in[2];
    const float* W1     = (const float*)d_in[3];
    const float* b1     = (const float*)d_in[4];
    const float* g1     = (const float*)d_in[5];
    const float* be1    = (const float*)d_in[6];
    const float* W2     = (const float*)d_in[7];
    const float* b2     = (const float*)d_in[8];
    const float* g2     = (const float*)d_in[9];
    const float* be2    = (const float*)d_in[10];
    const float* W3     = (const float*)d_in[11];
    const float* b3     = (const float*)d_in[12];
    const float* bscale = (const float*)d_in[13];
    float* out = (float*)d_out;

    cudaFuncSetAttribute(gab_kernel, cudaFuncAttributeMaxDynamicSharedMemorySize,
                         (int)sizeof(Smem));
    dim3 grid(NP / PCHUNK, NG / 8, BATCH);
    gab_kernel<<<grid, 256, sizeof(Smem)>>>(scene, poses, W1, b1, g1, be1,
                                            W2, b2, g2, be2, W3, b3, bscale, out);
}